// round 17
// baseline (speedup 1.0000x reference)
#include <cuda_runtime.h>
#include <math.h>

// ---------------- problem constants ----------------
#define NHEADS 8
#define NPOINTS 8
#define NDZ 4
#define DMODEL 256
#define NCAM 6
#define NQ 4096
#define FH 56
#define FW 100
#define FHW (FH*FW)          // 5600
#define BNQ (NCAM*NQ)        // 24576 rows of (cam,query)
#define MV  (NCAM*FHW)       // 33600 rows of (cam,pixel)
#define MVP 33664            // MV padded to multiple of 128

typedef unsigned long long ull;

// packed fp32x2 FMA: d = a*b + d elementwise on (lo,hi) f32 halves.
// Exact fp32 .rn semantics — numerically identical to two scalar FFMAs.
#define FMA_F32X2(d, a, b) \
    asm("fma.rn.f32x2 %0, %1, %2, %0;" : "+l"(d) : "l"(a), "l"(b))

__device__ __forceinline__ ull dup_f32(float f) {
    unsigned int u = __float_as_uint(f);
    return ((ull)u << 32) | u;
}

// ---------------- scratch (device globals; no allocation) ----------------
__device__ float g_value[MVP*DMODEL];          // value projection (pad rows junk, never read)
__device__ float g_off  [BNQ*NHEADS*NPOINTS*2];// raw sampling offsets (pixels)
__device__ float g_attn [BNQ*NHEADS*NPOINTS];  // attention logits
__device__ float g_out  [BNQ*DMODEL];          // sampled+weighted output
__device__ float g_qa   [BNQ*DMODEL];          // attn-out projection
__device__ float g_slots[NQ*DMODEL];           // masked camera-combine
__device__ float g_valid[NCAM*NQ];             // per (cam,q) validity

// ============================================================================
// GEMM variant A: BM=128, BN=64, BK=16, 8x4 microtile (narrow-N / small-M)
// ============================================================================
template<int N, int K>
__device__ __forceinline__ void sgemm_bt64(const float* __restrict__ A,
                                           const float* __restrict__ B,
                                           const float* __restrict__ bias,
                                           float* __restrict__ C)
{
    constexpr int BM = 128, BN = 64, BK = 16;
    __shared__ float sA[2][BK][BM];
    __shared__ float sB[2][BK][BN];

    const int t  = threadIdx.x;
    const int tx = t & 15;
    const int ty = t >> 4;
    const int m0 = blockIdx.y * BM;
    const int n0 = blockIdx.x * BN;

    const int alr = t >> 1;
    const int alk = (t & 1) * 8;
    const int blr = t >> 2;
    const int blk = (t & 3) * 4;

    const float* Ap = A + (size_t)(m0 + alr) * K + alk;
    const float* Bp = B + (size_t)(n0 + blr) * K + blk;

    float4 a0 = *(const float4*)(Ap);
    float4 a1 = *(const float4*)(Ap + 4);
    float4 b0 = *(const float4*)(Bp);

    float acc[8][4] = {};
    int buf = 0;

    for (int k0 = 0; k0 < K; k0 += BK) {
        sA[buf][alk+0][alr] = a0.x; sA[buf][alk+1][alr] = a0.y;
        sA[buf][alk+2][alr] = a0.z; sA[buf][alk+3][alr] = a0.w;
        sA[buf][alk+4][alr] = a1.x; sA[buf][alk+5][alr] = a1.y;
        sA[buf][alk+6][alr] = a1.z; sA[buf][alk+7][alr] = a1.w;
        sB[buf][blk+0][blr] = b0.x; sB[buf][blk+1][blr] = b0.y;
        sB[buf][blk+2][blr] = b0.z; sB[buf][blk+3][blr] = b0.w;
        __syncthreads();

        if (k0 + BK < K) {
            a0 = *(const float4*)(Ap + k0 + BK);
            a1 = *(const float4*)(Ap + k0 + BK + 4);
            b0 = *(const float4*)(Bp + k0 + BK);
        }

        #pragma unroll
        for (int kk = 0; kk < BK; kk++) {
            float4 ra0 = *(const float4*)(&sA[buf][kk][ty * 8]);
            float4 ra1 = *(const float4*)(&sA[buf][kk][ty * 8 + 4]);
            float4 rb  = *(const float4*)(&sB[buf][kk][tx * 4]);
            float av[8] = {ra0.x, ra0.y, ra0.z, ra0.w, ra1.x, ra1.y, ra1.z, ra1.w};
            float bv[4] = {rb.x, rb.y, rb.z, rb.w};
            #pragma unroll
            for (int i = 0; i < 8; i++)
                #pragma unroll
                for (int j = 0; j < 4; j++)
                    acc[i][j] += av[i] * bv[j];
        }
        buf ^= 1;
    }

    float4 bb = *(const float4*)(bias + n0 + tx * 4);
    #pragma unroll
    for (int i = 0; i < 8; i++) {
        float4 o;
        o.x = acc[i][0] + bb.x; o.y = acc[i][1] + bb.y;
        o.z = acc[i][2] + bb.z; o.w = acc[i][3] + bb.w;
        *(float4*)(C + (size_t)(m0 + ty * 8 + i) * N + n0 + tx * 4) = o;
    }
}

// ============================================================================
// Fused off+attn GEMM: A = queries + pos_emb computed on the fly.
// ============================================================================
__global__ __launch_bounds__(256) void k_gemm_offattn(
    const float* __restrict__ queries, const float* __restrict__ pos,
    const float* __restrict__ Woff, const float* __restrict__ boff,
    const float* __restrict__ Watt, const float* __restrict__ batt)
{
    constexpr int BM = 128, BN = 64, BK = 16, K = DMODEL;
    __shared__ float sA[2][BK][BM];
    __shared__ float sB[2][BK][BN];

    const int t  = threadIdx.x;
    const int tx = t & 15;
    const int ty = t >> 4;
    const int m0 = blockIdx.y * BM;
    const int n0 = blockIdx.x * BN;             // 0,64,128
    const bool is_off = (n0 < 128);
    const float* B    = is_off ? Woff : Watt;
    const float* bias = is_off ? boff : batt;
    const int nb      = is_off ? n0 : 0;

    const int alr = t >> 1;
    const int alk = (t & 1) * 8;
    const int blr = t >> 2;
    const int blk = (t & 3) * 4;

    const int gm = m0 + alr;
    const float* Ap = queries + (size_t)gm * K + alk;
    const float* Pp = pos + (size_t)(gm & (NQ - 1)) * K + alk;
    const float* Bp = B + (size_t)(nb + blr) * K + blk;

    float4 a0 = *(const float4*)(Ap);
    float4 a1 = *(const float4*)(Ap + 4);
    float4 p0 = *(const float4*)(Pp);
    float4 p1 = *(const float4*)(Pp + 4);
    float4 b0 = *(const float4*)(Bp);

    float acc[8][4] = {};
    int buf = 0;

    for (int k0 = 0; k0 < K; k0 += BK) {
        sA[buf][alk+0][alr] = a0.x + p0.x; sA[buf][alk+1][alr] = a0.y + p0.y;
        sA[buf][alk+2][alr] = a0.z + p0.z; sA[buf][alk+3][alr] = a0.w + p0.w;
        sA[buf][alk+4][alr] = a1.x + p1.x; sA[buf][alk+5][alr] = a1.y + p1.y;
        sA[buf][alk+6][alr] = a1.z + p1.z; sA[buf][alk+7][alr] = a1.w + p1.w;
        sB[buf][blk+0][blr] = b0.x; sB[buf][blk+1][blr] = b0.y;
        sB[buf][blk+2][blr] = b0.z; sB[buf][blk+3][blr] = b0.w;
        __syncthreads();

        if (k0 + BK < K) {
            a0 = *(const float4*)(Ap + k0 + BK);
            a1 = *(const float4*)(Ap + k0 + BK + 4);
            p0 = *(const float4*)(Pp + k0 + BK);
            p1 = *(const float4*)(Pp + k0 + BK + 4);
            b0 = *(const float4*)(Bp + k0 + BK);
        }

        #pragma unroll
        for (int kk = 0; kk < BK; kk++) {
            float4 ra0 = *(const float4*)(&sA[buf][kk][ty * 8]);
            float4 ra1 = *(const float4*)(&sA[buf][kk][ty * 8 + 4]);
            float4 rb  = *(const float4*)(&sB[buf][kk][tx * 4]);
            float av[8] = {ra0.x, ra0.y, ra0.z, ra0.w, ra1.x, ra1.y, ra1.z, ra1.w};
            float bv[4] = {rb.x, rb.y, rb.z, rb.w};
            #pragma unroll
            for (int i = 0; i < 8; i++)
                #pragma unroll
                for (int j = 0; j < 4; j++)
                    acc[i][j] += av[i] * bv[j];
        }
        buf ^= 1;
    }

    float4 bb = *(const float4*)(bias + nb + tx * 4);
    #pragma unroll
    for (int i = 0; i < 8; i++) {
        float4 o;
        o.x = acc[i][0] + bb.x; o.y = acc[i][1] + bb.y;
        o.z = acc[i][2] + bb.z; o.w = acc[i][3] + bb.w;
        const int row = m0 + ty * 8 + i;
        if (is_off)
            *(float4*)(g_off  + (size_t)row * 128 + n0 + tx * 4) = o;
        else
            *(float4*)(g_attn + (size_t)row * 64 + tx * 4) = o;
    }
}

// ============================================================================
// Value GEMM: BM=128, BN=128, BK=16, 8x8 microtile via packed f32x2 FMA.
// A staged as duplicated {a,a} ull pairs; B pairs read as consecutive floats.
// A tile read straight from features (cam,c,pix) + lvl/cam embeddings fused.
// ============================================================================
__global__ __launch_bounds__(256) void k_gemm_value(
    const float* __restrict__ feat, const float* __restrict__ lvl,
    const float* __restrict__ came, const float* __restrict__ W,
    const float* __restrict__ bias)
{
    constexpr int BM = 128, BN = 128, BK = 16, K = DMODEL;
    __shared__ ull   sA2[2][BK][BM];   // {a,a} pairs  (32 KB)
    __shared__ float sB [2][BK][BN];   // scalar B     (16 KB)

    const int t  = threadIdx.x;
    const int tx = t & 15;               // cols tx*8
    const int ty = t >> 4;               // rows ty*8
    const int m0 = blockIdx.y * BM;
    const int n0 = blockIdx.x * BN;

    // A loader: tp = pixel-row in tile, tc selects channel half (8 ch each)
    const int tp = t & 127;
    const int tc = t >> 7;
    const int gm = m0 + tp;
    const bool arow_ok = (gm < MV);
    int cam = 0, p = 0;
    if (arow_ok) { cam = gm / FHW; p = gm - cam * FHW; }
    const float* fb = feat + (size_t)cam * (DMODEL * FHW) + p;
    const float* eb_l = lvl;
    const float* eb_c = came + cam * DMODEL;

    // B loader
    const int blr = t >> 1;
    const int blk = (t & 1) * 8;
    const float* Bp = W + (size_t)(n0 + blr) * K + blk;

    float a_pre[8];
    #pragma unroll
    for (int j = 0; j < 8; j++) {
        const int c = tc * 8 + j;
        a_pre[j] = arow_ok ? (fb[(size_t)c * FHW] + eb_l[c] + eb_c[c]) : 0.0f;
    }
    float4 b0 = *(const float4*)(Bp);
    float4 b1 = *(const float4*)(Bp + 4);

    ull acc2[8][4] = {};                 // acc2[i][j2] = (C[i][2j2], C[i][2j2+1])
    int buf = 0;

    for (int k0 = 0; k0 < K; k0 += BK) {
        #pragma unroll
        for (int j = 0; j < 8; j++)
            sA2[buf][tc * 8 + j][tp] = dup_f32(a_pre[j]);
        sB[buf][blk+0][blr] = b0.x; sB[buf][blk+1][blr] = b0.y;
        sB[buf][blk+2][blr] = b0.z; sB[buf][blk+3][blr] = b0.w;
        sB[buf][blk+4][blr] = b1.x; sB[buf][blk+5][blr] = b1.y;
        sB[buf][blk+6][blr] = b1.z; sB[buf][blk+7][blr] = b1.w;
        __syncthreads();

        if (k0 + BK < K) {
            const int kn = k0 + BK;
            #pragma unroll
            for (int j = 0; j < 8; j++) {
                const int c = kn + tc * 8 + j;
                a_pre[j] = arow_ok ? (fb[(size_t)c * FHW] + eb_l[c] + eb_c[c]) : 0.0f;
            }
            b0 = *(const float4*)(Bp + kn);
            b1 = *(const float4*)(Bp + kn + 4);
        }

        #pragma unroll
        for (int kk = 0; kk < BK; kk++) {
            const ulonglong2* pa = (const ulonglong2*)&sA2[buf][kk][ty * 8];
            const ulonglong2* pb = (const ulonglong2*)&sB[buf][kk][tx * 8];
            ulonglong2 av0 = pa[0], av1 = pa[1], av2 = pa[2], av3 = pa[3];
            ulonglong2 bv0 = pb[0], bv1 = pb[1];
            ull a2[8] = {av0.x, av0.y, av1.x, av1.y, av2.x, av2.y, av3.x, av3.y};
            ull b2[4] = {bv0.x, bv0.y, bv1.x, bv1.y};
            #pragma unroll
            for (int i = 0; i < 8; i++)
                #pragma unroll
                for (int j = 0; j < 4; j++)
                    FMA_F32X2(acc2[i][j], a2[i], b2[j]);
        }
        buf ^= 1;
    }

    float bbv[8];
    *(float4*)(bbv)     = *(const float4*)(bias + n0 + tx * 8);
    *(float4*)(bbv + 4) = *(const float4*)(bias + n0 + tx * 8 + 4);
    #pragma unroll
    for (int i = 0; i < 8; i++) {
        float* Crow = g_value + (size_t)(m0 + ty * 8 + i) * DMODEL + n0 + tx * 8;
        float o[8];
        #pragma unroll
        for (int j = 0; j < 4; j++) {
            unsigned int lo, hi;
            asm("mov.b64 {%0, %1}, %2;" : "=r"(lo), "=r"(hi) : "l"(acc2[i][j]));
            o[2*j]   = __uint_as_float(lo) + bbv[2*j];
            o[2*j+1] = __uint_as_float(hi) + bbv[2*j+1];
        }
        *(float4*)(Crow)     = *(float4*)(o);
        *(float4*)(Crow + 4) = *(float4*)(o + 4);
    }
}

// ============================================================================
// attn_out GEMM: BM=128, BN=128, BK=16, 8x8 microtile via packed f32x2 FMA.
// ============================================================================
__global__ __launch_bounds__(256) void k_gemm_attnout(
    const float* __restrict__ W, const float* __restrict__ bias)
{
    constexpr int BM = 128, BN = 128, BK = 16, K = DMODEL;
    __shared__ ull   sA2[2][BK][BM];   // {a,a} pairs  (32 KB)
    __shared__ float sB [2][BK][BN];   // scalar B     (16 KB)

    const int t  = threadIdx.x;
    const int tx = t & 15;
    const int ty = t >> 4;
    const int m0 = blockIdx.y * BM;
    const int n0 = blockIdx.x * BN;

    const int alr = t >> 1;
    const int alk = (t & 1) * 8;
    const float* Ap = g_out + (size_t)(m0 + alr) * K + alk;
    const float* Bp = W + (size_t)(n0 + alr) * K + alk;

    float4 a0 = *(const float4*)(Ap);
    float4 a1 = *(const float4*)(Ap + 4);
    float4 b0 = *(const float4*)(Bp);
    float4 b1 = *(const float4*)(Bp + 4);

    ull acc2[8][4] = {};
    int buf = 0;

    for (int k0 = 0; k0 < K; k0 += BK) {
        sA2[buf][alk+0][alr] = dup_f32(a0.x); sA2[buf][alk+1][alr] = dup_f32(a0.y);
        sA2[buf][alk+2][alr] = dup_f32(a0.z); sA2[buf][alk+3][alr] = dup_f32(a0.w);
        sA2[buf][alk+4][alr] = dup_f32(a1.x); sA2[buf][alk+5][alr] = dup_f32(a1.y);
        sA2[buf][alk+6][alr] = dup_f32(a1.z); sA2[buf][alk+7][alr] = dup_f32(a1.w);
        sB[buf][alk+0][alr] = b0.x; sB[buf][alk+1][alr] = b0.y;
        sB[buf][alk+2][alr] = b0.z; sB[buf][alk+3][alr] = b0.w;
        sB[buf][alk+4][alr] = b1.x; sB[buf][alk+5][alr] = b1.y;
        sB[buf][alk+6][alr] = b1.z; sB[buf][alk+7][alr] = b1.w;
        __syncthreads();

        if (k0 + BK < K) {
            a0 = *(const float4*)(Ap + k0 + BK);
            a1 = *(const float4*)(Ap + k0 + BK + 4);
            b0 = *(const float4*)(Bp + k0 + BK);
            b1 = *(const float4*)(Bp + k0 + BK + 4);
        }

        #pragma unroll
        for (int kk = 0; kk < BK; kk++) {
            const ulonglong2* pa = (const ulonglong2*)&sA2[buf][kk][ty * 8];
            const ulonglong2* pb = (const ulonglong2*)&sB[buf][kk][tx * 8];
            ulonglong2 av0 = pa[0], av1 = pa[1], av2 = pa[2], av3 = pa[3];
            ulonglong2 bv0 = pb[0], bv1 = pb[1];
            ull a2[8] = {av0.x, av0.y, av1.x, av1.y, av2.x, av2.y, av3.x, av3.y};
            ull b2[4] = {bv0.x, bv0.y, bv1.x, bv1.y};
            #pragma unroll
            for (int i = 0; i < 8; i++)
                #pragma unroll
                for (int j = 0; j < 4; j++)
                    FMA_F32X2(acc2[i][j], a2[i], b2[j]);
        }
        buf ^= 1;
    }

    float bbv[8];
    *(float4*)(bbv)     = *(const float4*)(bias + n0 + tx * 8);
    *(float4*)(bbv + 4) = *(const float4*)(bias + n0 + tx * 8 + 4);
    #pragma unroll
    for (int i = 0; i < 8; i++) {
        float* Crow = g_qa + (size_t)(m0 + ty * 8 + i) * DMODEL + n0 + tx * 8;
        float o[8];
        #pragma unroll
        for (int j = 0; j < 4; j++) {
            unsigned int lo, hi;
            asm("mov.b64 {%0, %1}, %2;" : "=r"(lo), "=r"(hi) : "l"(acc2[i][j]));
            o[2*j]   = __uint_as_float(lo) + bbv[2*j];
            o[2*j+1] = __uint_as_float(hi) + bbv[2*j+1];
        }
        *(float4*)(Crow)     = *(float4*)(o);
        *(float4*)(Crow + 4) = *(float4*)(o + 4);
    }
}

// final = slots @ W_out^T + b_out
__global__ __launch_bounds__(256) void k_gemm_final(const float* W, const float* b, float* C) {
    sgemm_bt64<DMODEL, DMODEL>(g_slots, W, b, C);
}

// ---------------- validity: any over z of bev_mask[0,cam,q,z,0] ----------------
__global__ void k_valid(const int* __restrict__ mask) {
    int i = blockIdx.x * blockDim.x + threadIdx.x;
    if (i >= NCAM * NQ) return;
    const int* mp = mask + (size_t)i * (NDZ * 2);
    g_valid[i] = (mp[0] | mp[2] | mp[4] | mp[6]) ? 1.0f : 0.0f;
}

// ============================================================================
// Sampling: one block of 256 threads per (cam,query) row.
// Phase 1 (64 threads = head*point): softmax + coords + clamped corner
//   indices/weights -> smem. Phase 2 (256 threads = channel): gather + FMA.
// ============================================================================
__global__ __launch_bounds__(256) void k_sample(const float* __restrict__ refpts) {
    __shared__ int   s_idx[NHEADS * NPOINTS][4];
    __shared__ float s_w  [NHEADS * NPOINTS][4];

    const int m   = blockIdx.x;
    const int tid = threadIdx.x;
    const int cam = m >> 12;

    if (tid < NHEADS * NPOINTS) {
        const int p = tid & 7;
        float lg = g_attn[(size_t)m * (NHEADS * NPOINTS) + tid];
        float mx = lg;
        #pragma unroll
        for (int o = 4; o >= 1; o >>= 1)
            mx = fmaxf(mx, __shfl_xor_sync(0xffffffffu, mx, o));
        float e = __expf(lg - mx);
        float ss = e;
        #pragma unroll
        for (int o = 4; o >= 1; o >>= 1)
            ss += __shfl_xor_sync(0xffffffffu, ss, o);
        const float wq = e / ss;

        const int z = p & 3;
        const float ox = g_off[(size_t)m * (NHEADS * NPOINTS * 2) + tid * 2 + 0];
        const float oy = g_off[(size_t)m * (NHEADS * NPOINTS * 2) + tid * 2 + 1];
        const float rx = refpts[(size_t)m * (NDZ * 2) + z * 2 + 0];
        const float ry = refpts[(size_t)m * (NDZ * 2) + z * 2 + 1];
        const float x = rx * (float)FW + ox - 0.5f;
        const float y = ry * (float)FH + oy - 0.5f;

        const float x0f = floorf(x), y0f = floorf(y);
        const int x0 = (int)x0f, y0 = (int)y0f;
        const int x1 = x0 + 1,  y1 = y0 + 1;
        const float wx1 = x - x0f, wx0 = 1.0f - wx1;
        const float wy1 = y - y0f, wy0 = 1.0f - wy1;
        const float vx0 = (x0 >= 0 && x0 < FW) ? 1.0f : 0.0f;
        const float vx1 = (x1 >= 0 && x1 < FW) ? 1.0f : 0.0f;
        const float vy0 = (y0 >= 0 && y0 < FH) ? 1.0f : 0.0f;
        const float vy1 = (y1 >= 0 && y1 < FH) ? 1.0f : 0.0f;
        const int cx0 = min(max(x0, 0), FW - 1);
        const int cx1 = min(max(x1, 0), FW - 1);
        const int cy0 = min(max(y0, 0), FH - 1);
        const int cy1 = min(max(y1, 0), FH - 1);
        s_idx[tid][0] = cy0 * FW + cx0;
        s_idx[tid][1] = cy0 * FW + cx1;
        s_idx[tid][2] = cy1 * FW + cx0;
        s_idx[tid][3] = cy1 * FW + cx1;
        s_w[tid][0] = wq * wx0 * wy0 * vx0 * vy0;
        s_w[tid][1] = wq * wx1 * wy0 * vx1 * vy0;
        s_w[tid][2] = wq * wx0 * wy1 * vx0 * vy1;
        s_w[tid][3] = wq * wx1 * wy1 * vx1 * vy1;
    }
    __syncthreads();

    const int c = tid;
    const int h = c >> 5;
    const float* vb = g_value + ((size_t)cam * FHW) * DMODEL + c;

    float acc = 0.0f;
    #pragma unroll
    for (int p = 0; p < NPOINTS; p++) {
        const int base = h * NPOINTS + p;
        const int   i0 = s_idx[base][0], i1 = s_idx[base][1];
        const int   i2 = s_idx[base][2], i3 = s_idx[base][3];
        const float w0 = s_w[base][0], w1 = s_w[base][1];
        const float w2 = s_w[base][2], w3 = s_w[base][3];
        acc += w0 * vb[(size_t)i0 * DMODEL];
        acc += w1 * vb[(size_t)i1 * DMODEL];
        acc += w2 * vb[(size_t)i2 * DMODEL];
        acc += w3 * vb[(size_t)i3 * DMODEL];
    }
    g_out[(size_t)m * DMODEL + c] = acc;
}

// ---------------- masked camera combine with count normalization ----------------
__global__ void k_combine() {
    int i = blockIdx.x * blockDim.x + threadIdx.x;
    if (i >= NQ * DMODEL) return;
    const int qi = i >> 8;
    const int c  = i & 255;
    float s = 0.0f, cnt = 0.0f;
    #pragma unroll
    for (int cam = 0; cam < NCAM; cam++) {
        const float v = g_valid[cam * NQ + qi];
        cnt += v;
        s += v * g_qa[((size_t)(cam * NQ + qi)) * DMODEL + c];
    }
    g_slots[i] = s / fmaxf(cnt, 1.0f);
}

// ---------------- launch ----------------
extern "C" void kernel_launch(void* const* d_in, const int* in_sizes, int n_in,
                              void* d_out, int out_size)
{
    const float* queries   = (const float*)d_in[0];
    const float* pos_emb   = (const float*)d_in[1];
    const float* lvl_emb   = (const float*)d_in[2];
    const float* cam_emb   = (const float*)d_in[3];
    const float* features  = (const float*)d_in[4];
    const float* refpts    = (const float*)d_in[5];
    const float* W_off     = (const float*)d_in[6];
    const float* b_off     = (const float*)d_in[7];
    const float* W_attn    = (const float*)d_in[8];
    const float* b_attn    = (const float*)d_in[9];
    const float* W_val     = (const float*)d_in[10];
    const float* b_val     = (const float*)d_in[11];
    const float* W_ao      = (const float*)d_in[12];
    const float* b_ao      = (const float*)d_in[13];
    const float* W_out     = (const float*)d_in[14];
    const float* b_out     = (const float*)d_in[15];
    const int*   bev_mask  = (const int*)d_in[16];
    float* out = (float*)d_out;

    // 1. off+attn projections (qp fused into A load)
    k_gemm_offattn<<<dim3(3, BNQ / 128), 256>>>(queries, pos_emb,
                                                W_off, b_off, W_attn, b_attn);

    // 2. value projection, f32x2 packed FMA, transpose+embeddings fused
    k_gemm_value<<<dim3(DMODEL / 128, MVP / 128), 256>>>(features, lvl_emb, cam_emb,
                                                         W_val, b_val);

    // 3. per (cam,q) validity
    k_valid<<<(NCAM * NQ + 255) / 256, 256>>>(bev_mask);

    // 4. softmax + bilinear sampling + weighted accumulate (one block per row)
    k_sample<<<BNQ, 256>>>(refpts);

    // 5. qa = out @ W_attn_out^T + b_attn_out, f32x2 packed FMA
    k_gemm_attnout<<<dim3(DMODEL / 128, BNQ / 128), 256>>>(W_ao, b_ao);

    // 6. masked camera combine
    k_combine<<<(NQ * DMODEL + 255) / 256, 256>>>();

    // 7. final = slots @ W_out^T + b_out -> d_out
    k_gemm_final<<<dim3(DMODEL / 64, NQ / 128), 256>>>(W_out, b_out, out);
}